// round 2
// baseline (speedup 1.0000x reference)
#include <cuda_runtime.h>

#define B_  32
#define S_  512
#define D_  512
#define H_  8
#define DK_ 64
#define NEG_INF_ (-1e30f)

// Scratch (device globals: allocation-free per harness rules)
__device__ float g_Q[B_*H_*S_*DK_];       // [B,H,S,DK]
__device__ float g_K[B_*H_*S_*DK_];
__device__ float g_V[B_*H_*S_*DK_];
__device__ float g_heads[B_*S_*H_*DK_];   // [B,S,H*DK] (concat heads)

__device__ __forceinline__ float neg_inf_f() { return __int_as_float(0xff800000); }

// ---------------------------------------------------------------------------
// Kernel 1: QKV projections.  For (b,h,mat): C[128s x 64k] = X[128s x 512d] @ W[512d x 64k] + bias
// grid (4 s-tiles, B*H=256, 3 mats), block 256.  BM=128 BN=64 BK=32, 8x4 microtile.
// ---------------------------------------------------------------------------
__global__ __launch_bounds__(256) void qkv_kernel(
    const float* __restrict__ x,
    const float* __restrict__ Wq, const float* __restrict__ Wk,
    const float* __restrict__ Wv, const float* __restrict__ bias)
{
    __shared__ float Xs[128 * 36];   // 128 rows x 32 cols, pad to 36 (16B-aligned rows)
    __shared__ float Ws[32 * 68];    // 32 rows x 64 cols, pad to 68

    const int t  = threadIdx.x;
    const int s0 = blockIdx.x * 128;
    const int b  = blockIdx.y >> 3;
    const int h  = blockIdx.y & 7;

    const float* W  = (blockIdx.z == 0) ? Wq : (blockIdx.z == 1 ? Wk : Wv);
    float*       Cg = (blockIdx.z == 0) ? g_Q : (blockIdx.z == 1 ? g_K : g_V);

    const float* A  = x + (size_t)b * S_ * D_;
    const float* Bm = W + (size_t)h * D_ * DK_;
    float*       C  = Cg + ((size_t)(b * H_ + h) * S_ + s0) * DK_;

    const int ty = t >> 4, tx = t & 15;
    const int r0 = ty * 8, c0 = tx * 4;

    float acc[8][4];
    #pragma unroll
    for (int i = 0; i < 8; i++) {
        acc[i][0] = 0.f; acc[i][1] = 0.f; acc[i][2] = 0.f; acc[i][3] = 0.f;
    }

    for (int d0 = 0; d0 < D_; d0 += 32) {
        // X tile 128x32 : 1024 float4 slots / 256 threads = 4 each
        #pragma unroll
        for (int i = 0; i < 4; i++) {
            int v = t + 256 * i;
            int r = v >> 3, c4 = v & 7;
            float4 xv = *(const float4*)&A[(size_t)(s0 + r) * D_ + d0 + c4 * 4];
            *(float4*)&Xs[r * 36 + c4 * 4] = xv;
        }
        // W tile 32x64 : 512 float4 slots / 256 threads = 2 each
        #pragma unroll
        for (int i = 0; i < 2; i++) {
            int v = t + 256 * i;
            int r = v >> 4, c4 = v & 15;
            float4 wv = *(const float4*)&Bm[(size_t)(d0 + r) * DK_ + c4 * 4];
            *(float4*)&Ws[r * 68 + c4 * 4] = wv;
        }
        __syncthreads();

        #pragma unroll 8
        for (int kk = 0; kk < 32; kk++) {
            float a[8];
            #pragma unroll
            for (int i = 0; i < 8; i++) a[i] = Xs[(r0 + i) * 36 + kk];
            float4 b4 = *(const float4*)&Ws[kk * 68 + c0];
            #pragma unroll
            for (int i = 0; i < 8; i++) {
                acc[i][0] += a[i] * b4.x;
                acc[i][1] += a[i] * b4.y;
                acc[i][2] += a[i] * b4.z;
                acc[i][3] += a[i] * b4.w;
            }
        }
        __syncthreads();
    }

    const float bs = bias[0];
    #pragma unroll
    for (int i = 0; i < 8; i++) {
        float4 o = make_float4(acc[i][0] + bs, acc[i][1] + bs,
                               acc[i][2] + bs, acc[i][3] + bs);
        *(float4*)&C[(size_t)(r0 + i) * DK_ + c0] = o;
    }
}

// ---------------------------------------------------------------------------
// Kernel 2: fused masked-softmax attention, flash-style online softmax.
// grid (4 q-tiles of 128, B*H=256), block 128: one query row per thread.
// ---------------------------------------------------------------------------
__global__ __launch_bounds__(128) void attn_kernel(const int* __restrict__ mask)
{
    __shared__ float Ks[64 * 64];
    __shared__ float Vs[64 * 64];
    __shared__ float mk[64];

    const int t  = threadIdx.x;
    const int s  = blockIdx.x * 128 + t;   // query index within sequence
    const int bh = blockIdx.y;
    const int b  = bh >> 3;
    const int h  = bh & 7;

    const float* Qp = g_Q + ((size_t)bh * S_ + s) * DK_;
    const float* Kp = g_K + (size_t)bh * S_ * DK_;
    const float* Vp = g_V + (size_t)bh * S_ * DK_;
    const float scale = 0.125f;            // 1/sqrt(DK)

    float q[64];
    #pragma unroll
    for (int k = 0; k < 64; k += 4) {
        float4 v = *(const float4*)&Qp[k];
        q[k] = v.x; q[k+1] = v.y; q[k+2] = v.z; q[k+3] = v.w;
    }

    float o[64];
    #pragma unroll
    for (int k = 0; k < 64; k++) o[k] = 0.f;
    float m = neg_inf_f();
    float l = 0.f;

    for (int t0 = 0; t0 < S_; t0 += 64) {
        // cooperative load of K/V tiles (64x64 each): 1024 float4 / 128 thr = 8 each
        #pragma unroll
        for (int i = 0; i < 8; i++) {
            int v = t + 128 * i;
            int r = v >> 4, c4 = v & 15;
            *(float4*)&Ks[r * 64 + c4 * 4] = *(const float4*)&Kp[(size_t)(t0 + r) * 64 + c4 * 4];
            *(float4*)&Vs[r * 64 + c4 * 4] = *(const float4*)&Vp[(size_t)(t0 + r) * 64 + c4 * 4];
        }
        if (t < 64) mk[t] = (float)mask[b * S_ + t0 + t];
        __syncthreads();

        for (int j0 = 0; j0 < 64; j0 += 8) {
            float sc[8];
            #pragma unroll
            for (int j = 0; j < 8; j++) {
                const float* kr = &Ks[(j0 + j) * 64];
                float a0 = 0.f, a1 = 0.f, a2 = 0.f, a3 = 0.f;
                #pragma unroll
                for (int k = 0; k < 64; k += 16) {
                    float4 k0 = *(const float4*)&kr[k];
                    float4 k1 = *(const float4*)&kr[k + 4];
                    float4 k2 = *(const float4*)&kr[k + 8];
                    float4 k3 = *(const float4*)&kr[k + 12];
                    a0 += q[k]    * k0.x + q[k+1]  * k0.y + q[k+2]  * k0.z + q[k+3]  * k0.w;
                    a1 += q[k+4]  * k1.x + q[k+5]  * k1.y + q[k+6]  * k1.z + q[k+7]  * k1.w;
                    a2 += q[k+8]  * k2.x + q[k+9]  * k2.y + q[k+10] * k2.z + q[k+11] * k2.w;
                    a3 += q[k+12] * k3.x + q[k+13] * k3.y + q[k+14] * k3.z + q[k+15] * k3.w;
                }
                float dot = (a0 + a1) + (a2 + a3);
                sc[j] = (mk[j0 + j] != 0.f) ? dot * scale : NEG_INF_;
            }
            float mloc = sc[0];
            #pragma unroll
            for (int j = 1; j < 8; j++) mloc = fmaxf(mloc, sc[j]);
            if (mloc > m) {
                float corr = __expf(m - mloc);   // exp(-inf)=0 on first hit; o is 0 anyway
                m = mloc;
                l *= corr;
                #pragma unroll
                for (int k = 0; k < 64; k++) o[k] *= corr;
            }
            #pragma unroll
            for (int j = 0; j < 8; j++) {
                float p = __expf(sc[j] - m);
                l += p;
                const float* vr = &Vs[(j0 + j) * 64];
                #pragma unroll
                for (int k = 0; k < 64; k += 4) {
                    float4 vv = *(const float4*)&vr[k];
                    o[k]   += p * vv.x;
                    o[k+1] += p * vv.y;
                    o[k+2] += p * vv.z;
                    o[k+3] += p * vv.w;
                }
            }
        }
        __syncthreads();
    }

    // All-masked rows: every sc = -1e30 -> p = 1 each -> l = S, uniform probs (matches ref)
    float inv = 1.f / l;
    float* Hp = g_heads + ((size_t)(b * S_ + s)) * (H_ * DK_) + h * DK_;
    #pragma unroll
    for (int k = 0; k < 64; k += 4) {
        float4 ov = make_float4(o[k] * inv, o[k+1] * inv, o[k+2] * inv, o[k+3] * inv);
        *(float4*)&Hp[k] = ov;
    }
}

// ---------------------------------------------------------------------------
// Kernel 3: output projection.  out[16384,512] = heads[16384,512] @ Wo[512,512] + bias
// grid (128 row-tiles, 8 col-tiles), block 256.  Same tiling as kernel 1.
// ---------------------------------------------------------------------------
__global__ __launch_bounds__(256) void out_kernel(
    const float* __restrict__ Wo, const float* __restrict__ bias,
    float* __restrict__ out)
{
    __shared__ float As[128 * 36];
    __shared__ float Bs[32 * 68];

    const int t  = threadIdx.x;
    const int m0 = blockIdx.x * 128;
    const int n0 = blockIdx.y * 64;

    const int ty = t >> 4, tx = t & 15;
    const int r0 = ty * 8, c0 = tx * 4;

    float acc[8][4];
    #pragma unroll
    for (int i = 0; i < 8; i++) {
        acc[i][0] = 0.f; acc[i][1] = 0.f; acc[i][2] = 0.f; acc[i][3] = 0.f;
    }

    for (int d0 = 0; d0 < D_; d0 += 32) {
        #pragma unroll
        for (int i = 0; i < 4; i++) {
            int v = t + 256 * i;
            int r = v >> 3, c4 = v & 7;
            *(float4*)&As[r * 36 + c4 * 4] =
                *(const float4*)&g_heads[(size_t)(m0 + r) * (H_*DK_) + d0 + c4 * 4];
        }
        #pragma unroll
        for (int i = 0; i < 2; i++) {
            int v = t + 256 * i;
            int r = v >> 4, c4 = v & 15;
            *(float4*)&Bs[r * 68 + c4 * 4] =
                *(const float4*)&Wo[(size_t)(d0 + r) * D_ + n0 + c4 * 4];
        }
        __syncthreads();

        #pragma unroll 8
        for (int kk = 0; kk < 32; kk++) {
            float a[8];
            #pragma unroll
            for (int i = 0; i < 8; i++) a[i] = As[(r0 + i) * 36 + kk];
            float4 b4 = *(const float4*)&Bs[kk * 68 + c0];
            #pragma unroll
            for (int i = 0; i < 8; i++) {
                acc[i][0] += a[i] * b4.x;
                acc[i][1] += a[i] * b4.y;
                acc[i][2] += a[i] * b4.z;
                acc[i][3] += a[i] * b4.w;
            }
        }
        __syncthreads();
    }

    const float bs = bias[0];
    #pragma unroll
    for (int i = 0; i < 8; i++) {
        float4 o = make_float4(acc[i][0] + bs, acc[i][1] + bs,
                               acc[i][2] + bs, acc[i][3] + bs);
        *(float4*)&out[(size_t)(m0 + r0 + i) * D_ + n0 + c0] = o;
    }
}

// ---------------------------------------------------------------------------
extern "C" void kernel_launch(void* const* d_in, const int* in_sizes, int n_in,
                              void* d_out, int out_size)
{
    const float* x    = (const float*)d_in[0];
    const int*   mask = (const int*)  d_in[1];
    const float* Wq   = (const float*)d_in[2];
    const float* Wk   = (const float*)d_in[3];
    const float* Wv   = (const float*)d_in[4];
    const float* Wo   = (const float*)d_in[5];
    const float* bias = (const float*)d_in[6];
    float*       out  = (float*)d_out;

    qkv_kernel<<<dim3(4, 256, 3), 256>>>(x, Wq, Wk, Wv, bias);
    attn_kernel<<<dim3(4, 256), 128>>>(mask);
    out_kernel<<<dim3(128, 8), 256>>>(Wo, bias, out);
}

// round 7
// speedup vs baseline: 2.7056x; 2.7056x over previous
#include <cuda_runtime.h>
#include <cstdint>

#define B_  32
#define S_  512
#define D_  512
#define H_  8
#define DK_ 64
#define NEG_INF_ (-1e30f)

// Scratch (device globals: allocation-free per harness rules)
__device__ float g_Q[B_*H_*S_*DK_];       // [B,H,S,DK]
__device__ float g_K[B_*H_*S_*DK_];
__device__ float g_V[B_*H_*S_*DK_];
__device__ float g_heads[B_*S_*H_*DK_];   // [B,S,H*DK]

__device__ __forceinline__ uint32_t f2tf(float f) {
    uint32_t u;
    asm("cvt.rna.tf32.f32 %0, %1;" : "=r"(u) : "f"(f));
    return u;
}
__device__ __forceinline__ float f2tf_f(float f) { return __uint_as_float(f2tf(f)); }

// D += A(16x8, row) * B(8x8, col); tf32 inputs as b32 regs, fp32 accum.
__device__ __forceinline__ void mma8(float* c,
    uint32_t a0, uint32_t a1, uint32_t a2, uint32_t a3,
    uint32_t b0, uint32_t b1)
{
    asm volatile(
        "mma.sync.aligned.m16n8k8.row.col.f32.tf32.tf32.f32 "
        "{%0,%1,%2,%3},{%4,%5,%6,%7},{%8,%9},{%0,%1,%2,%3};"
        : "+f"(c[0]), "+f"(c[1]), "+f"(c[2]), "+f"(c[3])
        : "r"(a0), "r"(a1), "r"(a2), "r"(a3), "r"(b0), "r"(b1));
}

// ---------------------------------------------------------------------------
// Kernel 1: QKV projections, tf32 MMA.
// Per block: C[128 x 128] = X[128 x 512] @ W[512 x 128] (+bias), where the 128
// output cols = 2 heads x DK=64 of one of {Q,K,V}.
// grid (4 s-tiles, B=32, 12 = 3 mats x 4 head-pairs), block 256 (8 warps x 16 rows).
// ---------------------------------------------------------------------------
__global__ __launch_bounds__(256) void qkv_mma(
    const float* __restrict__ x,
    const float* __restrict__ Wq, const float* __restrict__ Wk,
    const float* __restrict__ Wv, const float* __restrict__ bias)
{
    __shared__ float Xs[128 * 40];    // 128 x 32, stride 40 (A-frag conflict-free)
    __shared__ float Ws[32 * 136];    // 32 x 128, stride 136 (B-frag conflict-free)

    const int t    = threadIdx.x;
    const int warp = t >> 5, lane = t & 31;
    const int gid  = lane >> 2, tig = lane & 3;
    const int wrow = warp * 16;

    const int s0  = blockIdx.x * 128;
    const int b   = blockIdx.y;
    const int g   = blockIdx.z;
    const int mat = g >> 2;
    const int hp  = g & 3;            // head pair -> heads 2*hp, 2*hp+1

    const float* Wm = ((mat == 0) ? Wq : (mat == 1 ? Wk : Wv)) + (size_t)(2 * hp) * D_ * DK_;
    float*       Cg = (mat == 0) ? g_Q : (mat == 1 ? g_K : g_V);
    const float* A  = x + ((size_t)b * S_ + s0) * D_;

    float acc[16][4];
    #pragma unroll
    for (int nt = 0; nt < 16; nt++) { acc[nt][0]=0.f; acc[nt][1]=0.f; acc[nt][2]=0.f; acc[nt][3]=0.f; }

    for (int d0 = 0; d0 < D_; d0 += 32) {
        // X tile 128x32: 1024 float4 / 256 thr = 4 each
        #pragma unroll
        for (int i = 0; i < 4; i++) {
            int v = t + 256 * i;
            int r = v >> 3, c4 = v & 7;
            float4 xv = *(const float4*)&A[(size_t)r * D_ + d0 + c4 * 4];
            float* dst = &Xs[r * 40 + c4 * 4];
            dst[0]=f2tf_f(xv.x); dst[1]=f2tf_f(xv.y); dst[2]=f2tf_f(xv.z); dst[3]=f2tf_f(xv.w);
        }
        // W tile 32x128: 1024 float4 / 256 thr = 4 each
        #pragma unroll
        for (int i = 0; i < 4; i++) {
            int v = t + 256 * i;
            int row = v >> 5, c4 = v & 31;
            int n = c4 * 4;
            int hloc = n >> 6, k = n & 63;
            float4 wv = *(const float4*)&Wm[((size_t)hloc * D_ + d0 + row) * DK_ + k];
            float* dst = &Ws[row * 136 + n];
            dst[0]=f2tf_f(wv.x); dst[1]=f2tf_f(wv.y); dst[2]=f2tf_f(wv.z); dst[3]=f2tf_f(wv.w);
        }
        __syncthreads();

        #pragma unroll
        for (int ks = 0; ks < 4; ks++) {
            uint32_t a0 = __float_as_uint(Xs[(wrow + gid)     * 40 + ks * 8 + tig]);
            uint32_t a1 = __float_as_uint(Xs[(wrow + gid + 8) * 40 + ks * 8 + tig]);
            uint32_t a2 = __float_as_uint(Xs[(wrow + gid)     * 40 + ks * 8 + tig + 4]);
            uint32_t a3 = __float_as_uint(Xs[(wrow + gid + 8) * 40 + ks * 8 + tig + 4]);
            #pragma unroll
            for (int nt = 0; nt < 16; nt++) {
                uint32_t b0 = __float_as_uint(Ws[(ks * 8 + tig)     * 136 + nt * 8 + gid]);
                uint32_t b1 = __float_as_uint(Ws[(ks * 8 + tig + 4) * 136 + nt * 8 + gid]);
                mma8(acc[nt], a0, a1, a2, a3, b0, b1);
            }
        }
        __syncthreads();
    }

    const float bs = bias[0];
    const int row0 = s0 + wrow + gid;
    #pragma unroll
    for (int nt = 0; nt < 16; nt++) {
        int col = nt * 8 + 2 * tig;          // 0..126, pair stays within one head
        int hh  = col >> 6, kk = col & 63;
        float* base = Cg + ((size_t)(b * H_ + 2 * hp + hh) * S_) * DK_ + kk;
        *(float2*)&base[(size_t)row0 * DK_]       = make_float2(acc[nt][0] + bs, acc[nt][1] + bs);
        *(float2*)&base[(size_t)(row0 + 8) * DK_] = make_float2(acc[nt][2] + bs, acc[nt][3] + bs);
    }
}

// ---------------------------------------------------------------------------
// Kernel 2: fused attention (tf32 MMA scores + PV, fp32 online softmax).
// grid (4 q-tiles of 128, 256 bh), block 256 = 8 warps x 16 query rows.
// Dynamic smem: Ks[64x72] | Vs[64x72] | Ps[128x72] | mks[64]
// ---------------------------------------------------------------------------
#define ATTN_SMEM_FLOATS (64*72 + 64*72 + 128*72 + 64)

__global__ __launch_bounds__(256) void attn_mma(const int* __restrict__ mask)
{
    extern __shared__ float sm[];
    float* Ks  = sm;
    float* Vs  = sm + 64 * 72;
    float* Ps  = sm + 2 * 64 * 72;
    float* mks = sm + 2 * 64 * 72 + 128 * 72;

    const int t    = threadIdx.x;
    const int warp = t >> 5, lane = t & 31;
    const int gid  = lane >> 2, tig = lane & 3;
    const int wrow = warp * 16;

    const int q0 = blockIdx.x * 128;
    const int bh = blockIdx.y;
    const int b  = bh >> 3, h = bh & 7;

    const float* Qp = g_Q + ((size_t)bh * S_ + q0) * DK_;
    const float* Kp = g_K + (size_t)bh * S_ * DK_;
    const float* Vp = g_V + (size_t)bh * S_ * DK_;

    // Stage Q (128x64) into Ps, then pull per-warp A-fragments into registers.
    #pragma unroll
    for (int i = 0; i < 8; i++) {
        int v = t + 256 * i;
        int r = v >> 4, c4 = v & 15;
        float4 qv = *(const float4*)&Qp[(size_t)r * DK_ + c4 * 4];
        float* dst = &Ps[r * 72 + c4 * 4];
        dst[0]=f2tf_f(qv.x); dst[1]=f2tf_f(qv.y); dst[2]=f2tf_f(qv.z); dst[3]=f2tf_f(qv.w);
    }
    __syncthreads();

    uint32_t qa[8][4];
    #pragma unroll
    for (int ks = 0; ks < 8; ks++) {
        qa[ks][0] = __float_as_uint(Ps[(wrow + gid)     * 72 + ks * 8 + tig]);
        qa[ks][1] = __float_as_uint(Ps[(wrow + gid + 8) * 72 + ks * 8 + tig]);
        qa[ks][2] = __float_as_uint(Ps[(wrow + gid)     * 72 + ks * 8 + tig + 4]);
        qa[ks][3] = __float_as_uint(Ps[(wrow + gid + 8) * 72 + ks * 8 + tig + 4]);
    }
    __syncthreads();

    float o[8][4];
    #pragma unroll
    for (int nt = 0; nt < 8; nt++) { o[nt][0]=0.f; o[nt][1]=0.f; o[nt][2]=0.f; o[nt][3]=0.f; }
    float m0 = __int_as_float(0xff800000);
    float m1 = m0;
    float l0 = 0.f, l1 = 0.f;

    for (int t0 = 0; t0 < S_; t0 += 64) {
        // K, V tiles (64x64 each): 4 float4 per thread per tile
        #pragma unroll
        for (int i = 0; i < 4; i++) {
            int v = t + 256 * i;
            int r = v >> 4, c4 = v & 15;
            float4 kv = *(const float4*)&Kp[(size_t)(t0 + r) * DK_ + c4 * 4];
            float4 vv = *(const float4*)&Vp[(size_t)(t0 + r) * DK_ + c4 * 4];
            float* dk = &Ks[r * 72 + c4 * 4];
            float* dv = &Vs[r * 72 + c4 * 4];
            dk[0]=f2tf_f(kv.x); dk[1]=f2tf_f(kv.y); dk[2]=f2tf_f(kv.z); dk[3]=f2tf_f(kv.w);
            dv[0]=f2tf_f(vv.x); dv[1]=f2tf_f(vv.y); dv[2]=f2tf_f(vv.z); dv[3]=f2tf_f(vv.w);
        }
        if (t < 64) mks[t] = (float)mask[b * S_ + t0 + t];
        __syncthreads();

        // Scores: S[128q x 64k] = Q @ K^T   (A=Q frags in regs, B from Ks)
        float s[8][4];
        #pragma unroll
        for (int nt = 0; nt < 8; nt++) { s[nt][0]=0.f; s[nt][1]=0.f; s[nt][2]=0.f; s[nt][3]=0.f; }
        #pragma unroll
        for (int ks = 0; ks < 8; ks++) {
            #pragma unroll
            for (int nt = 0; nt < 8; nt++) {
                uint32_t b0 = __float_as_uint(Ks[(nt * 8 + gid) * 72 + ks * 8 + tig]);
                uint32_t b1 = __float_as_uint(Ks[(nt * 8 + gid) * 72 + ks * 8 + tig + 4]);
                mma8(s[nt], qa[ks][0], qa[ks][1], qa[ks][2], qa[ks][3], b0, b1);
            }
        }

        // Scale + mask
        #pragma unroll
        for (int nt = 0; nt < 8; nt++) {
            int col = nt * 8 + 2 * tig;
            float mk0 = mks[col], mk1 = mks[col + 1];
            s[nt][0] = (mk0 != 0.f) ? s[nt][0] * 0.125f : NEG_INF_;
            s[nt][1] = (mk1 != 0.f) ? s[nt][1] * 0.125f : NEG_INF_;
            s[nt][2] = (mk0 != 0.f) ? s[nt][2] * 0.125f : NEG_INF_;
            s[nt][3] = (mk1 != 0.f) ? s[nt][3] * 0.125f : NEG_INF_;
        }

        // Row maxes (rows r=wrow+gid and r+8), quad reduction
        float ml0 = fmaxf(s[0][0], s[0][1]), ml1 = fmaxf(s[0][2], s[0][3]);
        #pragma unroll
        for (int nt = 1; nt < 8; nt++) {
            ml0 = fmaxf(ml0, fmaxf(s[nt][0], s[nt][1]));
            ml1 = fmaxf(ml1, fmaxf(s[nt][2], s[nt][3]));
        }
        ml0 = fmaxf(ml0, __shfl_xor_sync(0xffffffffu, ml0, 1));
        ml0 = fmaxf(ml0, __shfl_xor_sync(0xffffffffu, ml0, 2));
        ml1 = fmaxf(ml1, __shfl_xor_sync(0xffffffffu, ml1, 1));
        ml1 = fmaxf(ml1, __shfl_xor_sync(0xffffffffu, ml1, 2));

        float mn0 = fmaxf(m0, ml0), mn1 = fmaxf(m1, ml1);
        float c0 = __expf(m0 - mn0), c1 = __expf(m1 - mn1);
        m0 = mn0; m1 = mn1;
        #pragma unroll
        for (int nt = 0; nt < 8; nt++) {
            o[nt][0] *= c0; o[nt][1] *= c0;
            o[nt][2] *= c1; o[nt][3] *= c1;
        }

        // Exponentiate, row-sum, write P (tf32) to Ps
        float ps0 = 0.f, ps1 = 0.f;
        const int prow0 = (wrow + gid) * 72, prow1 = (wrow + gid + 8) * 72;
        #pragma unroll
        for (int nt = 0; nt < 8; nt++) {
            int col = nt * 8 + 2 * tig;
            float p00 = __expf(s[nt][0] - m0);
            float p01 = __expf(s[nt][1] - m0);
            float p10 = __expf(s[nt][2] - m1);
            float p11 = __expf(s[nt][3] - m1);
            ps0 += p00 + p01; ps1 += p10 + p11;
            *(float2*)&Ps[prow0 + col] = make_float2(f2tf_f(p00), f2tf_f(p01));
            *(float2*)&Ps[prow1 + col] = make_float2(f2tf_f(p10), f2tf_f(p11));
        }
        ps0 += __shfl_xor_sync(0xffffffffu, ps0, 1);
        ps0 += __shfl_xor_sync(0xffffffffu, ps0, 2);
        ps1 += __shfl_xor_sync(0xffffffffu, ps1, 1);
        ps1 += __shfl_xor_sync(0xffffffffu, ps1, 2);
        l0 = l0 * c0 + ps0;
        l1 = l1 * c1 + ps1;

        __syncwarp();   // P written by this warp's lanes, read cross-lane below

        // PV: O[128q x 64dk] += P @ V   (A from Ps, B from Vs)
        #pragma unroll
        for (int ks = 0; ks < 8; ks++) {
            uint32_t a0 = __float_as_uint(Ps[(wrow + gid)     * 72 + ks * 8 + tig]);
            uint32_t a1 = __float_as_uint(Ps[(wrow + gid + 8) * 72 + ks * 8 + tig]);
            uint32_t a2 = __float_as_uint(Ps[(wrow + gid)     * 72 + ks * 8 + tig + 4]);
            uint32_t a3 = __float_as_uint(Ps[(wrow + gid + 8) * 72 + ks * 8 + tig + 4]);
            #pragma unroll
            for (int nt = 0; nt < 8; nt++) {
                uint32_t b0 = __float_as_uint(Vs[(ks * 8 + tig)     * 72 + nt * 8 + gid]);
                uint32_t b1 = __float_as_uint(Vs[(ks * 8 + tig + 4) * 72 + nt * 8 + gid]);
                mma8(o[nt], a0, a1, a2, a3, b0, b1);
            }
        }
        __syncthreads();   // Ks/Vs/mks reused next iteration
    }

    const float inv0 = 1.f / l0, inv1 = 1.f / l1;
    const int q  = q0 + wrow + gid;
    float* Hp0 = g_heads + ((size_t)(b * S_ + q))     * (H_ * DK_) + h * DK_;
    float* Hp1 = g_heads + ((size_t)(b * S_ + q + 8)) * (H_ * DK_) + h * DK_;
    #pragma unroll
    for (int nt = 0; nt < 8; nt++) {
        int col = nt * 8 + 2 * tig;
        *(float2*)&Hp0[col] = make_float2(o[nt][0] * inv0, o[nt][1] * inv0);
        *(float2*)&Hp1[col] = make_float2(o[nt][2] * inv1, o[nt][3] * inv1);
    }
}

// ---------------------------------------------------------------------------
// Kernel 3: output projection, tf32 MMA.
// out[16384 x 512] = heads[16384 x 512] @ Wo[512 x 512] + bias
// grid (128 m-tiles, 4 n-tiles of 128), block 256.
// ---------------------------------------------------------------------------
__global__ __launch_bounds__(256) void out_mma(
    const float* __restrict__ Wo, const float* __restrict__ bias,
    float* __restrict__ out)
{
    __shared__ float As_[128 * 40];
    __shared__ float Bs_[32 * 136];

    const int t    = threadIdx.x;
    const int warp = t >> 5, lane = t & 31;
    const int gid  = lane >> 2, tig = lane & 3;
    const int wrow = warp * 16;

    const int m0 = blockIdx.x * 128;
    const int n0 = blockIdx.y * 128;

    float acc[16][4];
    #pragma unroll
    for (int nt = 0; nt < 16; nt++) { acc[nt][0]=0.f; acc[nt][1]=0.f; acc[nt][2]=0.f; acc[nt][3]=0.f; }

    for (int d0 = 0; d0 < D_; d0 += 32) {
        #pragma unroll
        for (int i = 0; i < 4; i++) {
            int v = t + 256 * i;
            int r = v >> 3, c4 = v & 7;
            float4 av = *(const float4*)&g_heads[(size_t)(m0 + r) * (H_*DK_) + d0 + c4 * 4];
            float* dst = &As_[r * 40 + c4 * 4];
            dst[0]=f2tf_f(av.x); dst[1]=f2tf_f(av.y); dst[2]=f2tf_f(av.z); dst[3]=f2tf_f(av.w);
        }
        #pragma unroll
        for (int i = 0; i < 4; i++) {
            int v = t + 256 * i;
            int row = v >> 5, c4 = v & 31;
            float4 wv = *(const float4*)&Wo[(size_t)(d0 + row) * D_ + n0 + c4 * 4];
            float* dst = &Bs_[row * 136 + c4 * 4];
            dst[0]=f2tf_f(wv.x); dst[1]=f2tf_f(wv.y); dst[2]=f2tf_f(wv.z); dst[3]=f2tf_f(wv.w);
        }
        __syncthreads();

        #pragma unroll
        for (int ks = 0; ks < 4; ks++) {
            uint32_t a0 = __float_as_uint(As_[(wrow + gid)     * 40 + ks * 8 + tig]);
            uint32_t a1 = __float_as_uint(As_[(wrow + gid + 8) * 40 + ks * 8 + tig]);
            uint32_t a2 = __float_as_uint(As_[(wrow + gid)     * 40 + ks * 8 + tig + 4]);
            uint32_t a3 = __float_as_uint(As_[(wrow + gid + 8) * 40 + ks * 8 + tig + 4]);
            #pragma unroll
            for (int nt = 0; nt < 16; nt++) {
                uint32_t b0 = __float_as_uint(Bs_[(ks * 8 + tig)     * 136 + nt * 8 + gid]);
                uint32_t b1 = __float_as_uint(Bs_[(ks * 8 + tig + 4) * 136 + nt * 8 + gid]);
                mma8(acc[nt], a0, a1, a2, a3, b0, b1);
            }
        }
        __syncthreads();
    }

    const float bs = bias[0];
    const int row0 = m0 + wrow + gid;
    #pragma unroll
    for (int nt = 0; nt < 16; nt++) {
        int col = n0 + nt * 8 + 2 * tig;
        *(float2*)&out[(size_t)row0 * D_ + col]       = make_float2(acc[nt][0] + bs, acc[nt][1] + bs);
        *(float2*)&out[(size_t)(row0 + 8) * D_ + col] = make_float2(acc[nt][2] + bs, acc[nt][3] + bs);
    }
}

// ---------------------------------------------------------------------------
extern "C" void kernel_launch(void* const* d_in, const int* in_sizes, int n_in,
                              void* d_out, int out_size)
{
    const float* x    = (const float*)d_in[0];
    const int*   mask = (const int*)  d_in[1];
    const float* Wq   = (const float*)d_in[2];
    const float* Wk   = (const float*)d_in[3];
    const float* Wv   = (const float*)d_in[4];
    const float* Wo   = (const float*)d_in[5];
    const float* bias = (const float*)d_in[6];
    float*       out  = (float*)d_out;

    static bool attr_set = false;
    if (!attr_set) {
        cudaFuncSetAttribute(attn_mma, cudaFuncAttributeMaxDynamicSharedMemorySize,
                             ATTN_SMEM_FLOATS * (int)sizeof(float));
        attr_set = true;
    }

    qkv_mma<<<dim3(4, 32, 12), 256>>>(x, Wq, Wk, Wv, bias);
    attn_mma<<<dim3(4, 256), 256, ATTN_SMEM_FLOATS * sizeof(float)>>>(mask);
    out_mma<<<dim3(128, 4), 256>>>(Wo, bias, out);
}